// round 9
// baseline (speedup 1.0000x reference)
#include <cuda_runtime.h>
#include <cuda_fp16.h>
#include <mma.h>
#include <math.h>

using namespace nvcuda;

#define NN   50000
#define NE   800000
#define ET   850000
#define FIN  128
#define HID  64
#define NG   512
#define SLOPE 0.2f
#define PRE_BLOCKS 512
#define NCHUNK 196   // ceil(NN/256)

// ---------------- scratch ----------------
__device__ __half g_hh[NN * HID];     // transformed features (fp16, gathered)
__device__ __half g_out[NN * HID];    // normalized layer output (fp16)
__device__ float g_asrc[NN];
__device__ float g_adst[NN];
__device__ int   g_cnt[NN];           // ZERO at rest; s12 resets after use
__device__ int   g_rofs[NN];          // LOCAL exclusive scan (per 256-chunk)
__device__ int   g_pos[NN];
__device__ unsigned g_edge[ET];       // src (u16 low) | eatt fp16 bits (high)
__device__ float g_pooled[NG * HID];
__device__ float g_gcnt[NG];
__device__ float g_scal[8];           // [0]=sum(ew), [1..3]=c per layer
__device__ int   g_bsum[256];
__device__ int   g_bpre[256];
__device__ float g_part[PRE_BLOCKS];
__device__ unsigned g_s1done;         // zero at rest; last block resets

// ---------------- k_pre: zero pooled/gcnt + c scalars + ew partial sums ----------
__global__ void k_pre(const float* __restrict__ We0, const float* __restrict__ ae0,
                      const float* __restrict__ We1, const float* __restrict__ ae1,
                      const float* __restrict__ We2, const float* __restrict__ ae2,
                      const float* __restrict__ ew) {
    __shared__ float sm[256];
    int b = blockIdx.x, t = threadIdx.x;
    int i = b * 256 + t;
    if (i < NG * HID) g_pooled[i] = 0.f;
    if (i < NG) g_gcnt[i] = 0.f;

    float acc = 0.f;
    for (int idx = i; idx < NE; idx += PRE_BLOCKS * 256) acc += ew[idx];
    sm[t] = acc;
    __syncthreads();
    for (int off = 128; off > 0; off >>= 1) {
        if (t < off) sm[t] += sm[t + off];
        __syncthreads();
    }
    if (t == 0) g_part[b] = sm[0];
    __syncthreads();

    if (b < 3) {
        const float* We = (b == 0) ? We0 : (b == 1) ? We1 : We2;
        const float* ae = (b == 0) ? ae0 : (b == 1) ? ae1 : ae2;
        sm[t] = (t < HID) ? We[t] * ae[t] : 0.f;
        __syncthreads();
        for (int off = 128; off > 0; off >>= 1) {
            if (t < off) sm[t] += sm[t + off];
            __syncthreads();
        }
        if (t == 0) g_scal[1 + b] = sm[0];
    }
}

// histogram over real edges; g_cnt starts at 0 (reset by s12 each run)
__global__ void k_hist(const int* __restrict__ eidx) {
    int q = blockIdx.x * blockDim.x + threadIdx.x;
    if (q >= NE / 4) return;
    int4 d4 = reinterpret_cast<const int4*>(eidx + NE)[q];
    atomicAdd(&g_cnt[d4.x], 1);
    atomicAdd(&g_cnt[d4.y], 1);
    atomicAdd(&g_cnt[d4.z], 1);
    atomicAdd(&g_cnt[d4.w], 1);
}

// fused: local scans (+self-loop +1, reset cnt) ; last block scans block sums
// and finalizes edge-weight total. Grid MUST be NCHUNK.
__global__ void k_s12() {
    __shared__ int sh[256];
    __shared__ int s_last;
    int t = threadIdx.x;
    int i = blockIdx.x * 256 + t;
    int v = 0;
    if (i < NN) {
        v = g_cnt[i] + 1;      // fold self-loop
        g_cnt[i] = 0;          // reset for next replay
    }
    sh[t] = v;
    __syncthreads();
    for (int off = 1; off < 256; off <<= 1) {
        int x = (t >= off) ? sh[t - off] : 0;
        __syncthreads();
        sh[t] += x;
        __syncthreads();
    }
    if (i < NN) {
        int r = sh[t] - v;
        g_rofs[i] = r;
        g_pos[i] = r;
    }
    if (t == 255) g_bsum[blockIdx.x] = sh[t];
    __threadfence();
    __syncthreads();
    if (t == 0) {
        unsigned done = atomicAdd(&g_s1done, 1u);
        s_last = (done == (unsigned)gridDim.x - 1u);
    }
    __syncthreads();
    if (!s_last) return;

    // ---- last block: scan block sums + ew total ----
    if (t == 0) g_s1done = 0;
    int bv = (t < NCHUNK) ? g_bsum[t] : 0;
    sh[t] = bv;
    __syncthreads();
    for (int off = 1; off < 256; off <<= 1) {
        int x = (t >= off) ? sh[t - off] : 0;
        __syncthreads();
        sh[t] += x;
        __syncthreads();
    }
    if (t < NCHUNK) g_bpre[t] = sh[t] - bv;
    __syncthreads();
    __shared__ float sf[256];
    sf[t] = g_part[t] + g_part[t + 256];
    __syncthreads();
    for (int off = 128; off > 0; off >>= 1) {
        if (t < off) sf[t] += sf[t + off];
        __syncthreads();
    }
    if (t == 0) g_scal[0] = sf[0];
}

__global__ void k_scat(const int* __restrict__ eidx, const float* __restrict__ ew) {
    int e = blockIdx.x * blockDim.x + threadIdx.x;
    if (e >= ET) return;
    int s, d;
    float a;
    if (e < NE) {
        s = eidx[e];
        d = eidx[NE + e];
        a = ew[e];
    } else {
        s = d = e - NE;
        a = g_scal[0] * (1.0f / (float)NE);
    }
    int p = atomicAdd(&g_pos[d], 1) + g_bpre[d >> 8];
    unsigned rec = (unsigned)s |
                   ((unsigned)__half_as_ushort(__float2half_rn(a)) << 16);
    g_edge[p] = rec;
}

// ---------------- HMMA GEMM (wmma) + attention logits ----------------
#define LDA 136   // half
#define LDB 72    // half
#define LDC 68    // float

__global__ void k_gemm(const float* __restrict__ X, int ext, int Fin,
                       const float* __restrict__ W,
                       const float* __restrict__ bias_prev,
                       const float* __restrict__ as_, const float* __restrict__ ad_) {
    __shared__ __align__(16) char sbuf[18432 + 17408];
    __half* Bs = reinterpret_cast<__half*>(sbuf);            // [K][LDB]
    __half* As = reinterpret_cast<__half*>(sbuf + 18432);    // [64][LDA]
    float*  Cs = reinterpret_cast<float*>(sbuf + 18432);     // [64][LDC] alias

    int t = threadIdx.x;
    int w = t >> 5;
    int n0 = blockIdx.x * 64;

    if (ext) {
        int r = t >> 1;
        int n = n0 + r;
        const float4* xrow = reinterpret_cast<const float4*>(X + (size_t)n * FIN);
        #pragma unroll
        for (int f = 0; f < 16; f++) {
            int c4 = (t & 1) * 16 + f;
            float4 v = (n < NN) ? xrow[c4] : make_float4(0, 0, 0, 0);
            __half2* p = reinterpret_cast<__half2*>(&As[r * LDA + c4 * 4]);
            p[0] = __floats2half2_rn(v.x, v.y);
            p[1] = __floats2half2_rn(v.z, v.w);
        }
    } else {
        int r = t >> 1;
        int n = n0 + r;
        int cbase = (t & 1) * 32;
        #pragma unroll
        for (int c = 0; c < 16; c++) {
            int col = cbase + c * 2;
            float2 hv = {0.f, 0.f};
            if (n < NN)
                hv = __half22float2(*reinterpret_cast<const __half2*>(
                    &g_out[((size_t)n << 6) + col]));
            float bx = bias_prev[col], by = bias_prev[col + 1];
            hv.x = fmaxf(hv.x + bx, 0.f);
            hv.y = fmaxf(hv.y + by, 0.f);
            *reinterpret_cast<__half2*>(&As[r * LDA + col]) = __floats2half2_rn(hv.x, hv.y);
        }
    }

    {
        int total4 = Fin * HID / 4;
        const float4* w4 = reinterpret_cast<const float4*>(W);
        for (int idx = t; idx < total4; idx += 128) {
            int r = idx >> 4;
            int c4 = idx & 15;
            float4 v = w4[idx];
            __half2* p = reinterpret_cast<__half2*>(&Bs[r * LDB + c4 * 4]);
            p[0] = __floats2half2_rn(v.x, v.y);
            p[1] = __floats2half2_rn(v.z, v.w);
        }
    }
    __syncthreads();

    wmma::fragment<wmma::accumulator, 16, 16, 16, float> acc[4];
    #pragma unroll
    for (int nt = 0; nt < 4; nt++) wmma::fill_fragment(acc[nt], 0.f);

    int ksteps = Fin >> 4;
    for (int kt = 0; kt < ksteps; kt++) {
        wmma::fragment<wmma::matrix_a, 16, 16, 16, __half, wmma::row_major> af;
        wmma::load_matrix_sync(af, &As[(w * 16) * LDA + kt * 16], LDA);
        #pragma unroll
        for (int nt = 0; nt < 4; nt++) {
            wmma::fragment<wmma::matrix_b, 16, 16, 16, __half, wmma::row_major> bf;
            wmma::load_matrix_sync(bf, &Bs[(kt * 16) * LDB + nt * 16], LDB);
            wmma::mma_sync(acc[nt], af, bf, acc[nt]);
        }
    }
    __syncthreads();

    #pragma unroll
    for (int nt = 0; nt < 4; nt++)
        wmma::store_matrix_sync(&Cs[(w * 16) * LDC + nt * 16], acc[nt], LDC,
                                wmma::mem_row_major);
    __syncthreads();

    {
        int r = t >> 1;
        int n = n0 + r;
        int cbase = (t & 1) * 32;
        float s = 0.f, d = 0.f;
        if (n < NN) {
            #pragma unroll
            for (int c = 0; c < 32; c += 2) {
                int col = cbase + c;
                float v0 = Cs[r * LDC + col];
                float v1 = Cs[r * LDC + col + 1];
                *reinterpret_cast<__half2*>(&g_hh[((size_t)n << 6) + col]) =
                    __floats2half2_rn(v0, v1);
                s = fmaf(v0, as_[col], s); s = fmaf(v1, as_[col + 1], s);
                d = fmaf(v0, ad_[col], d); d = fmaf(v1, ad_[col + 1], d);
            }
        }
        s += __shfl_xor_sync(0xffffffffu, s, 1);
        d += __shfl_xor_sync(0xffffffffu, d, 1);
        if ((t & 1) == 0 && n < NN) {
            g_asrc[n] = s;
            g_adst[n] = d;
        }
    }
}

// ---------------- segmented aggregation: warp per dst node ----------------
__global__ void k_agg(int layer, const int* __restrict__ batch,
                      const float* __restrict__ bias_last) {
    int n = blockIdx.x * 8 + (threadIdx.x >> 5);
    int lane = threadIdx.x & 31;
    int start = g_rofs[n] + g_bpre[n >> 8];
    int n2 = n + 1;
    int end = (n2 == NN) ? ET : g_rofs[n2] + g_bpre[n2 >> 8];
    float c = g_scal[1 + layer];
    float adstn = g_adst[n];

    float accx = 0.f, accy = 0.f, ssum = 0.f;

    for (int base = start; base < end; base += 32) {
        int i = base + lane;
        int s_l = 0;
        float alpha = 0.f;
        if (i < end) {
            unsigned ev = g_edge[i];
            s_l = (int)(ev & 0xFFFFu);
            float ea = __half2float(__ushort_as_half((unsigned short)(ev >> 16)));
            float al = g_asrc[s_l] + adstn + ea * c;
            al = fmaxf(al, 0.f) + SLOPE * fminf(al, 0.f);
            alpha = __expf(al);
        }
        ssum += alpha;
        int cnt = min(32, end - base);
        int jj = 0;
        for (; jj + 8 <= cnt; jj += 8) {
            __half2 hv[8];
            float aj[8];
            #pragma unroll
            for (int u = 0; u < 8; u++) {
                int sj = __shfl_sync(0xffffffffu, s_l, jj + u);
                aj[u]  = __shfl_sync(0xffffffffu, alpha, jj + u);
                hv[u] = *reinterpret_cast<const __half2*>(
                    &g_hh[((size_t)sj << 6) + (lane << 1)]);
            }
            #pragma unroll
            for (int u = 0; u < 8; u++) {
                float2 f = __half22float2(hv[u]);
                accx = fmaf(aj[u], f.x, accx);
                accy = fmaf(aj[u], f.y, accy);
            }
        }
        for (; jj < cnt; jj++) {
            int   sj = __shfl_sync(0xffffffffu, s_l, jj);
            float a2 = __shfl_sync(0xffffffffu, alpha, jj);
            float2 f = __half22float2(*reinterpret_cast<const __half2*>(
                &g_hh[((size_t)sj << 6) + (lane << 1)]));
            accx = fmaf(a2, f.x, accx);
            accy = fmaf(a2, f.y, accy);
        }
    }

    #pragma unroll
    for (int off = 16; off > 0; off >>= 1)
        ssum += __shfl_xor_sync(0xffffffffu, ssum, off);
    float inv = 1.f / (ssum + 1e-16f);
    float ox = accx * inv, oy = accy * inv;

    if (layer < 2) {
        *reinterpret_cast<__half2*>(&g_out[((size_t)n << 6) + (lane << 1)]) =
            __floats2half2_rn(ox, oy);
    } else {
        int g = batch[n];
        float2 bb = *reinterpret_cast<const float2*>(&bias_last[lane << 1]);
        float* p = &g_pooled[((size_t)g << 6) + (lane << 1)];
        asm volatile("red.global.add.v2.f32 [%0], {%1,%2};"
                     :: "l"(p), "f"(ox + bb.x), "f"(oy + bb.y) : "memory");
        if (lane == 0) atomicAdd(&g_gcnt[g], 1.f);
    }
}

// ---------------- readout ----------------
__global__ void k_read(const float* __restrict__ lin_w,
                       const float* __restrict__ lin_b, float* __restrict__ outp) {
    __shared__ float r[64];
    int g = blockIdx.x, j = threadIdx.x;
    float cnt = fmaxf(g_gcnt[g], 1.f);
    r[j] = (g_pooled[(size_t)g * HID + j] / cnt) * lin_w[j];
    __syncthreads();
    for (int off = 32; off > 0; off >>= 1) {
        if (j < off) r[j] += r[j + off];
        __syncthreads();
    }
    if (j == 0) {
        float v = r[0] + lin_b[0];
        outp[g] = 1.f / (1.f + expf(-v));
    }
}

// ---------------- stream/event resources (static init) ----------------
static cudaStream_t g_stream2;
static cudaEvent_t  g_evFork, g_evGemm1, g_evPre;
namespace {
struct InitRes {
    InitRes() {
        cudaStreamCreateWithFlags(&g_stream2, cudaStreamNonBlocking);
        cudaEventCreateWithFlags(&g_evFork,  cudaEventDisableTiming);
        cudaEventCreateWithFlags(&g_evGemm1, cudaEventDisableTiming);
        cudaEventCreateWithFlags(&g_evPre,   cudaEventDisableTiming);
    }
};
InitRes g_initres;
}

// ---------------- launch ----------------
extern "C" void kernel_launch(void* const* d_in, const int* in_sizes, int n_in,
                              void* d_out, int out_size) {
    const float* x     = (const float*)d_in[0];
    const int*   eidx  = (const int*)  d_in[1];
    const float* ew    = (const float*)d_in[2];
    const int*   batch = (const int*)  d_in[3];
    const float* W[3]  = {(const float*)d_in[4],  (const float*)d_in[10], (const float*)d_in[16]};
    const float* as_[3]= {(const float*)d_in[5],  (const float*)d_in[11], (const float*)d_in[17]};
    const float* ad_[3]= {(const float*)d_in[6],  (const float*)d_in[12], (const float*)d_in[18]};
    const float* We[3] = {(const float*)d_in[7],  (const float*)d_in[13], (const float*)d_in[19]};
    const float* ae[3] = {(const float*)d_in[8],  (const float*)d_in[14], (const float*)d_in[20]};
    const float* b[3]  = {(const float*)d_in[9],  (const float*)d_in[15], (const float*)d_in[21]};
    const float* lin_w = (const float*)d_in[22];
    const float* lin_b = (const float*)d_in[23];
    float* outp = (float*)d_out;

    const int GEMM_BLOCKS = (NN + 63) / 64;   // 782
    const int WARP_BLOCKS = NN / 8;           // 6250

    // fork stream2: gemm1 (independent), then pre
    cudaEventRecord(g_evFork, 0);
    cudaStreamWaitEvent(g_stream2, g_evFork, 0);
    k_gemm<<<GEMM_BLOCKS, 128, 0, g_stream2>>>(x, 1, FIN, W[0], b[0], as_[0], ad_[0]);
    cudaEventRecord(g_evGemm1, g_stream2);
    k_pre<<<PRE_BLOCKS, 256, 0, g_stream2>>>(We[0], ae[0], We[1], ae[1],
                                             We[2], ae[2], ew);
    cudaEventRecord(g_evPre, g_stream2);

    // capture stream: hist immediately (cnt starts 0), then scan (needs pre), scat
    k_hist<<<(NE / 4 + 255) / 256, 256>>>(eidx);
    cudaStreamWaitEvent(0, g_evPre, 0);
    k_s12<<<NCHUNK, 256>>>();
    k_scat<<<(ET + 255) / 256, 256>>>(eidx, ew);

    cudaStreamWaitEvent(0, g_evGemm1, 0);
    k_agg<<<WARP_BLOCKS, 256>>>(0, batch, b[2]);
    k_gemm<<<GEMM_BLOCKS, 128>>>(x, 0, HID, W[1], b[0], as_[1], ad_[1]);
    k_agg<<<WARP_BLOCKS, 256>>>(1, batch, b[2]);
    k_gemm<<<GEMM_BLOCKS, 128>>>(x, 0, HID, W[2], b[1], as_[2], ad_[2]);
    k_agg<<<WARP_BLOCKS, 256>>>(2, batch, b[2]);

    k_read<<<NG, 64>>>(lin_w, lin_b, outp);
}

// round 10
// speedup vs baseline: 1.0148x; 1.0148x over previous
#include <cuda_runtime.h>
#include <cuda_fp16.h>
#include <mma.h>
#include <math.h>

using namespace nvcuda;

#define NN   50000
#define NE   800000
#define ET   850000
#define FIN  128
#define HID  64
#define NG   512
#define SLOPE 0.2f
#define PRE_BLOCKS 512
#define NCHUNK 196   // ceil(NN/256)

// ---------------- scratch ----------------
__device__ __half g_hh[NN * HID];     // transformed features (fp16, gathered)
__device__ __half g_out[NN * HID];    // normalized layer output (fp16)
__device__ float g_asrc[NN];
__device__ float g_adst[NN];
__device__ int   g_cnt[NN];           // ZERO at rest; s12 resets after use
__device__ int   g_rofs[NN];          // LOCAL exclusive scan (per 256-chunk)
__device__ int   g_pos[NN];
__device__ unsigned g_edge[ET];       // src (u16 low) | eatt fp16 bits (high)
__device__ float g_pooled[NG * HID];
__device__ float g_gcnt[NG];
__device__ float g_scal[8];           // [0]=sum(ew), [1..3]=c per layer
__device__ int   g_bsum[256];
__device__ int   g_bpre[256];
__device__ float g_part[PRE_BLOCKS];
__device__ unsigned g_s1done;         // zero at rest; last block resets

// ---------------- k_pre: zero pooled/gcnt + c scalars + ew partial sums ----------
__global__ void k_pre(const float* __restrict__ We0, const float* __restrict__ ae0,
                      const float* __restrict__ We1, const float* __restrict__ ae1,
                      const float* __restrict__ We2, const float* __restrict__ ae2,
                      const float* __restrict__ ew) {
    __shared__ float sm[256];
    int b = blockIdx.x, t = threadIdx.x;
    int i = b * 256 + t;
    if (i < NG * HID) g_pooled[i] = 0.f;
    if (i < NG) g_gcnt[i] = 0.f;

    float acc = 0.f;
    for (int idx = i; idx < NE; idx += PRE_BLOCKS * 256) acc += ew[idx];
    sm[t] = acc;
    __syncthreads();
    for (int off = 128; off > 0; off >>= 1) {
        if (t < off) sm[t] += sm[t + off];
        __syncthreads();
    }
    if (t == 0) g_part[b] = sm[0];
    __syncthreads();

    if (b < 3) {
        const float* We = (b == 0) ? We0 : (b == 1) ? We1 : We2;
        const float* ae = (b == 0) ? ae0 : (b == 1) ? ae1 : ae2;
        sm[t] = (t < HID) ? We[t] * ae[t] : 0.f;
        __syncthreads();
        for (int off = 128; off > 0; off >>= 1) {
            if (t < off) sm[t] += sm[t + off];
            __syncthreads();
        }
        if (t == 0) g_scal[1 + b] = sm[0];
    }
}

// histogram over real edges; g_cnt starts at 0 (reset by s12 each run)
__global__ void k_hist(const int* __restrict__ eidx) {
    int q = blockIdx.x * blockDim.x + threadIdx.x;
    if (q >= NE / 4) return;
    int4 d4 = reinterpret_cast<const int4*>(eidx + NE)[q];
    atomicAdd(&g_cnt[d4.x], 1);
    atomicAdd(&g_cnt[d4.y], 1);
    atomicAdd(&g_cnt[d4.z], 1);
    atomicAdd(&g_cnt[d4.w], 1);
}

// fused: local scans (+self-loop +1, reset cnt) ; last block scans block sums
// and finalizes edge-weight total. Grid MUST be NCHUNK.
__global__ void k_s12() {
    __shared__ int sh[256];
    __shared__ int s_last;
    int t = threadIdx.x;
    int i = blockIdx.x * 256 + t;
    int v = 0;
    if (i < NN) {
        v = g_cnt[i] + 1;      // fold self-loop
        g_cnt[i] = 0;          // reset for next replay
    }
    sh[t] = v;
    __syncthreads();
    for (int off = 1; off < 256; off <<= 1) {
        int x = (t >= off) ? sh[t - off] : 0;
        __syncthreads();
        sh[t] += x;
        __syncthreads();
    }
    if (i < NN) {
        int r = sh[t] - v;
        g_rofs[i] = r;
        g_pos[i] = r;
    }
    if (t == 255) g_bsum[blockIdx.x] = sh[t];
    __threadfence();
    __syncthreads();
    if (t == 0) {
        unsigned done = atomicAdd(&g_s1done, 1u);
        s_last = (done == (unsigned)gridDim.x - 1u);
    }
    __syncthreads();
    if (!s_last) return;

    // ---- last block: scan block sums + ew total ----
    if (t == 0) g_s1done = 0;
    int bv = (t < NCHUNK) ? g_bsum[t] : 0;
    sh[t] = bv;
    __syncthreads();
    for (int off = 1; off < 256; off <<= 1) {
        int x = (t >= off) ? sh[t - off] : 0;
        __syncthreads();
        sh[t] += x;
        __syncthreads();
    }
    if (t < NCHUNK) g_bpre[t] = sh[t] - bv;
    __syncthreads();
    __shared__ float sf[256];
    sf[t] = g_part[t] + g_part[t + 256];
    __syncthreads();
    for (int off = 128; off > 0; off >>= 1) {
        if (t < off) sf[t] += sf[t + off];
        __syncthreads();
    }
    if (t == 0) g_scal[0] = sf[0];
}

__global__ void k_scat(const int* __restrict__ eidx, const float* __restrict__ ew) {
    int e = blockIdx.x * blockDim.x + threadIdx.x;
    if (e >= ET) return;
    int s, d;
    float a;
    if (e < NE) {
        s = eidx[e];
        d = eidx[NE + e];
        a = ew[e];
    } else {
        s = d = e - NE;
        a = g_scal[0] * (1.0f / (float)NE);
    }
    int p = atomicAdd(&g_pos[d], 1) + g_bpre[d >> 8];
    unsigned rec = (unsigned)s |
                   ((unsigned)__half_as_ushort(__float2half_rn(a)) << 16);
    g_edge[p] = rec;
}

// ---------------- HMMA GEMM (wmma) + attention logits ----------------
#define LDA 136   // half
#define LDB 72    // half
#define LDC 68    // float

__global__ void k_gemm(const float* __restrict__ X, int ext, int Fin,
                       const float* __restrict__ W,
                       const float* __restrict__ bias_prev,
                       const float* __restrict__ as_, const float* __restrict__ ad_) {
    __shared__ __align__(16) char sbuf[18432 + 17408];
    __half* Bs = reinterpret_cast<__half*>(sbuf);            // [K][LDB]
    __half* As = reinterpret_cast<__half*>(sbuf + 18432);    // [64][LDA]
    float*  Cs = reinterpret_cast<float*>(sbuf + 18432);     // [64][LDC] alias

    int t = threadIdx.x;
    int w = t >> 5;
    int n0 = blockIdx.x * 64;

    if (ext) {
        int r = t >> 1;
        int n = n0 + r;
        const float4* xrow = reinterpret_cast<const float4*>(X + (size_t)n * FIN);
        #pragma unroll
        for (int f = 0; f < 16; f++) {
            int c4 = (t & 1) * 16 + f;
            float4 v = (n < NN) ? xrow[c4] : make_float4(0, 0, 0, 0);
            __half2* p = reinterpret_cast<__half2*>(&As[r * LDA + c4 * 4]);
            p[0] = __floats2half2_rn(v.x, v.y);
            p[1] = __floats2half2_rn(v.z, v.w);
        }
    } else {
        int r = t >> 1;
        int n = n0 + r;
        int cbase = (t & 1) * 32;
        #pragma unroll
        for (int c = 0; c < 16; c++) {
            int col = cbase + c * 2;
            float2 hv = {0.f, 0.f};
            if (n < NN)
                hv = __half22float2(*reinterpret_cast<const __half2*>(
                    &g_out[((size_t)n << 6) + col]));
            float bx = bias_prev[col], by = bias_prev[col + 1];
            hv.x = fmaxf(hv.x + bx, 0.f);
            hv.y = fmaxf(hv.y + by, 0.f);
            *reinterpret_cast<__half2*>(&As[r * LDA + col]) = __floats2half2_rn(hv.x, hv.y);
        }
    }

    {
        int total4 = Fin * HID / 4;
        const float4* w4 = reinterpret_cast<const float4*>(W);
        for (int idx = t; idx < total4; idx += 128) {
            int r = idx >> 4;
            int c4 = idx & 15;
            float4 v = w4[idx];
            __half2* p = reinterpret_cast<__half2*>(&Bs[r * LDB + c4 * 4]);
            p[0] = __floats2half2_rn(v.x, v.y);
            p[1] = __floats2half2_rn(v.z, v.w);
        }
    }
    __syncthreads();

    wmma::fragment<wmma::accumulator, 16, 16, 16, float> acc[4];
    #pragma unroll
    for (int nt = 0; nt < 4; nt++) wmma::fill_fragment(acc[nt], 0.f);

    int ksteps = Fin >> 4;
    for (int kt = 0; kt < ksteps; kt++) {
        wmma::fragment<wmma::matrix_a, 16, 16, 16, __half, wmma::row_major> af;
        wmma::load_matrix_sync(af, &As[(w * 16) * LDA + kt * 16], LDA);
        #pragma unroll
        for (int nt = 0; nt < 4; nt++) {
            wmma::fragment<wmma::matrix_b, 16, 16, 16, __half, wmma::row_major> bf;
            wmma::load_matrix_sync(bf, &Bs[(kt * 16) * LDB + nt * 16], LDB);
            wmma::mma_sync(acc[nt], af, bf, acc[nt]);
        }
    }
    __syncthreads();

    #pragma unroll
    for (int nt = 0; nt < 4; nt++)
        wmma::store_matrix_sync(&Cs[(w * 16) * LDC + nt * 16], acc[nt], LDC,
                                wmma::mem_row_major);
    __syncthreads();

    {
        int r = t >> 1;
        int n = n0 + r;
        int cbase = (t & 1) * 32;
        float s = 0.f, d = 0.f;
        if (n < NN) {
            #pragma unroll
            for (int c = 0; c < 32; c += 2) {
                int col = cbase + c;
                float v0 = Cs[r * LDC + col];
                float v1 = Cs[r * LDC + col + 1];
                *reinterpret_cast<__half2*>(&g_hh[((size_t)n << 6) + col]) =
                    __floats2half2_rn(v0, v1);
                s = fmaf(v0, as_[col], s); s = fmaf(v1, as_[col + 1], s);
                d = fmaf(v0, ad_[col], d); d = fmaf(v1, ad_[col + 1], d);
            }
        }
        s += __shfl_xor_sync(0xffffffffu, s, 1);
        d += __shfl_xor_sync(0xffffffffu, d, 1);
        if ((t & 1) == 0 && n < NN) {
            g_asrc[n] = s;
            g_adst[n] = d;
        }
    }
}

// ---------------- segmented aggregation: warp per dst node ----------------
__global__ void k_agg(int layer, const int* __restrict__ batch,
                      const float* __restrict__ bias_last) {
    int n = blockIdx.x * 8 + (threadIdx.x >> 5);
    int lane = threadIdx.x & 31;
    int start = g_rofs[n] + g_bpre[n >> 8];
    int n2 = n + 1;
    int end = (n2 == NN) ? ET : g_rofs[n2] + g_bpre[n2 >> 8];
    float c = g_scal[1 + layer];
    float adstn = g_adst[n];

    float accx = 0.f, accy = 0.f, ssum = 0.f;

    for (int base = start; base < end; base += 32) {
        int i = base + lane;
        int s_l = 0;
        float alpha = 0.f;
        if (i < end) {
            unsigned ev = g_edge[i];
            s_l = (int)(ev & 0xFFFFu);
            float ea = __half2float(__ushort_as_half((unsigned short)(ev >> 16)));
            float al = g_asrc[s_l] + adstn + ea * c;
            al = fmaxf(al, 0.f) + SLOPE * fminf(al, 0.f);
            alpha = __expf(al);
        }
        ssum += alpha;
        int cnt = min(32, end - base);
        int jj = 0;
        for (; jj + 8 <= cnt; jj += 8) {
            __half2 hv[8];
            float aj[8];
            #pragma unroll
            for (int u = 0; u < 8; u++) {
                int sj = __shfl_sync(0xffffffffu, s_l, jj + u);
                aj[u]  = __shfl_sync(0xffffffffu, alpha, jj + u);
                hv[u] = *reinterpret_cast<const __half2*>(
                    &g_hh[((size_t)sj << 6) + (lane << 1)]);
            }
            #pragma unroll
            for (int u = 0; u < 8; u++) {
                float2 f = __half22float2(hv[u]);
                accx = fmaf(aj[u], f.x, accx);
                accy = fmaf(aj[u], f.y, accy);
            }
        }
        for (; jj < cnt; jj++) {
            int   sj = __shfl_sync(0xffffffffu, s_l, jj);
            float a2 = __shfl_sync(0xffffffffu, alpha, jj);
            float2 f = __half22float2(*reinterpret_cast<const __half2*>(
                &g_hh[((size_t)sj << 6) + (lane << 1)]));
            accx = fmaf(a2, f.x, accx);
            accy = fmaf(a2, f.y, accy);
        }
    }

    #pragma unroll
    for (int off = 16; off > 0; off >>= 1)
        ssum += __shfl_xor_sync(0xffffffffu, ssum, off);
    float inv = 1.f / (ssum + 1e-16f);
    float ox = accx * inv, oy = accy * inv;

    if (layer < 2) {
        *reinterpret_cast<__half2*>(&g_out[((size_t)n << 6) + (lane << 1)]) =
            __floats2half2_rn(ox, oy);
    } else {
        int g = batch[n];
        float2 bb = *reinterpret_cast<const float2*>(&bias_last[lane << 1]);
        float* p = &g_pooled[((size_t)g << 6) + (lane << 1)];
        asm volatile("red.global.add.v2.f32 [%0], {%1,%2};"
                     :: "l"(p), "f"(ox + bb.x), "f"(oy + bb.y) : "memory");
        if (lane == 0) atomicAdd(&g_gcnt[g], 1.f);
    }
}

// ---------------- readout ----------------
__global__ void k_read(const float* __restrict__ lin_w,
                       const float* __restrict__ lin_b, float* __restrict__ outp) {
    __shared__ float r[64];
    int g = blockIdx.x, j = threadIdx.x;
    float cnt = fmaxf(g_gcnt[g], 1.f);
    r[j] = (g_pooled[(size_t)g * HID + j] / cnt) * lin_w[j];
    __syncthreads();
    for (int off = 32; off > 0; off >>= 1) {
        if (j < off) r[j] += r[j + off];
        __syncthreads();
    }
    if (j == 0) {
        float v = r[0] + lin_b[0];
        outp[g] = 1.f / (1.f + expf(-v));
    }
}

// ---------------- stream/event resources (static init) ----------------
static cudaStream_t g_stream2;
static cudaEvent_t  g_evFork, g_evGemm1, g_evPre;
namespace {
struct InitRes {
    InitRes() {
        cudaStreamCreateWithFlags(&g_stream2, cudaStreamNonBlocking);
        cudaEventCreateWithFlags(&g_evFork,  cudaEventDisableTiming);
        cudaEventCreateWithFlags(&g_evGemm1, cudaEventDisableTiming);
        cudaEventCreateWithFlags(&g_evPre,   cudaEventDisableTiming);
    }
};
InitRes g_initres;
}

// ---------------- launch ----------------
extern "C" void kernel_launch(void* const* d_in, const int* in_sizes, int n_in,
                              void* d_out, int out_size) {
    const float* x     = (const float*)d_in[0];
    const int*   eidx  = (const int*)  d_in[1];
    const float* ew    = (const float*)d_in[2];
    const int*   batch = (const int*)  d_in[3];
    const float* W[3]  = {(const float*)d_in[4],  (const float*)d_in[10], (const float*)d_in[16]};
    const float* as_[3]= {(const float*)d_in[5],  (const float*)d_in[11], (const float*)d_in[17]};
    const float* ad_[3]= {(const float*)d_in[6],  (const float*)d_in[12], (const float*)d_in[18]};
    const float* We[3] = {(const float*)d_in[7],  (const float*)d_in[13], (const float*)d_in[19]};
    const float* ae[3] = {(const float*)d_in[8],  (const float*)d_in[14], (const float*)d_in[20]};
    const float* b[3]  = {(const float*)d_in[9],  (const float*)d_in[15], (const float*)d_in[21]};
    const float* lin_w = (const float*)d_in[22];
    const float* lin_b = (const float*)d_in[23];
    float* outp = (float*)d_out;

    const int GEMM_BLOCKS = (NN + 63) / 64;   // 782
    const int WARP_BLOCKS = NN / 8;           // 6250

    // fork stream2: pre FIRST (short, unblocks the scan), then gemm1
    cudaEventRecord(g_evFork, 0);
    cudaStreamWaitEvent(g_stream2, g_evFork, 0);
    k_pre<<<PRE_BLOCKS, 256, 0, g_stream2>>>(We[0], ae[0], We[1], ae[1],
                                             We[2], ae[2], ew);
    cudaEventRecord(g_evPre, g_stream2);
    k_gemm<<<GEMM_BLOCKS, 128, 0, g_stream2>>>(x, 1, FIN, W[0], b[0], as_[0], ad_[0]);
    cudaEventRecord(g_evGemm1, g_stream2);

    // capture stream: hist immediately (cnt starts 0), then scan (needs pre), scat
    k_hist<<<(NE / 4 + 255) / 256, 256>>>(eidx);
    cudaStreamWaitEvent(0, g_evPre, 0);
    k_s12<<<NCHUNK, 256>>>();
    k_scat<<<(ET + 255) / 256, 256>>>(eidx, ew);

    cudaStreamWaitEvent(0, g_evGemm1, 0);
    k_agg<<<WARP_BLOCKS, 256>>>(0, batch, b[2]);
    k_gemm<<<GEMM_BLOCKS, 128>>>(x, 0, HID, W[1], b[0], as_[1], ad_[1]);
    k_agg<<<WARP_BLOCKS, 256>>>(1, batch, b[2]);
    k_gemm<<<GEMM_BLOCKS, 128>>>(x, 0, HID, W[2], b[1], as_[2], ad_[2]);
    k_agg<<<WARP_BLOCKS, 256>>>(2, batch, b[2]);

    k_read<<<NG, 64>>>(lin_w, lin_b, outp);
}

// round 11
// speedup vs baseline: 1.1003x; 1.0843x over previous
#include <cuda_runtime.h>
#include <cuda_fp16.h>
#include <mma.h>
#include <math.h>

using namespace nvcuda;

#define NN   50000
#define NE   800000
#define ET   850000
#define FIN  128
#define HID  64
#define NG   512
#define SLOPE 0.2f
#define PRE_BLOCKS 512
#define NCHUNK 196   // ceil(NN/256)

// ---------------- scratch ----------------
__device__ __half g_hhA[NN * HID];
__device__ __half g_hhB[NN * HID];
__device__ float g_asrcA[NN], g_asrcB[NN];
__device__ float g_adstA[NN], g_adstB[NN];
__device__ int   g_cnt[NN];           // ZERO at rest; s12 resets after use
__device__ int   g_rofs[NN];
__device__ int   g_pos[NN];
__device__ unsigned g_edge[ET];       // src u16 | eatt fp16
__device__ float g_pooled[NG * HID];
__device__ float g_gcnt[NG];
__device__ float g_scal[8];
__device__ int   g_bsum[256];
__device__ int   g_bpre[256];
__device__ float g_part[PRE_BLOCKS];
__device__ unsigned g_s1done;

// ---------------- k_pre ----------------
__global__ void k_pre(const float* __restrict__ We0, const float* __restrict__ ae0,
                      const float* __restrict__ We1, const float* __restrict__ ae1,
                      const float* __restrict__ We2, const float* __restrict__ ae2,
                      const float* __restrict__ ew) {
    __shared__ float sm[256];
    int b = blockIdx.x, t = threadIdx.x;
    int i = b * 256 + t;
    if (i < NG * HID) g_pooled[i] = 0.f;
    if (i < NG) g_gcnt[i] = 0.f;

    float acc = 0.f;
    for (int idx = i; idx < NE; idx += PRE_BLOCKS * 256) acc += ew[idx];
    sm[t] = acc;
    __syncthreads();
    for (int off = 128; off > 0; off >>= 1) {
        if (t < off) sm[t] += sm[t + off];
        __syncthreads();
    }
    if (t == 0) g_part[b] = sm[0];
    __syncthreads();

    if (b < 3) {
        const float* We = (b == 0) ? We0 : (b == 1) ? We1 : We2;
        const float* ae = (b == 0) ? ae0 : (b == 1) ? ae1 : ae2;
        sm[t] = (t < HID) ? We[t] * ae[t] : 0.f;
        __syncthreads();
        for (int off = 128; off > 0; off >>= 1) {
            if (t < off) sm[t] += sm[t + off];
            __syncthreads();
        }
        if (t == 0) g_scal[1 + b] = sm[0];
    }
}

__global__ void k_hist(const int* __restrict__ eidx) {
    int q = blockIdx.x * blockDim.x + threadIdx.x;
    if (q >= NE / 4) return;
    int4 d4 = reinterpret_cast<const int4*>(eidx + NE)[q];
    atomicAdd(&g_cnt[d4.x], 1);
    atomicAdd(&g_cnt[d4.y], 1);
    atomicAdd(&g_cnt[d4.z], 1);
    atomicAdd(&g_cnt[d4.w], 1);
}

__global__ void k_s12() {
    __shared__ int sh[256];
    __shared__ int s_last;
    int t = threadIdx.x;
    int i = blockIdx.x * 256 + t;
    int v = 0;
    if (i < NN) {
        v = g_cnt[i] + 1;
        g_cnt[i] = 0;
    }
    sh[t] = v;
    __syncthreads();
    for (int off = 1; off < 256; off <<= 1) {
        int x = (t >= off) ? sh[t - off] : 0;
        __syncthreads();
        sh[t] += x;
        __syncthreads();
    }
    if (i < NN) {
        int r = sh[t] - v;
        g_rofs[i] = r;
        g_pos[i] = r;
    }
    if (t == 255) g_bsum[blockIdx.x] = sh[t];
    __threadfence();
    __syncthreads();
    if (t == 0) {
        unsigned done = atomicAdd(&g_s1done, 1u);
        s_last = (done == (unsigned)gridDim.x - 1u);
    }
    __syncthreads();
    if (!s_last) return;

    if (t == 0) g_s1done = 0;
    int bv = (t < NCHUNK) ? g_bsum[t] : 0;
    sh[t] = bv;
    __syncthreads();
    for (int off = 1; off < 256; off <<= 1) {
        int x = (t >= off) ? sh[t - off] : 0;
        __syncthreads();
        sh[t] += x;
        __syncthreads();
    }
    if (t < NCHUNK) g_bpre[t] = sh[t] - bv;
    __syncthreads();
    __shared__ float sf[256];
    sf[t] = g_part[t] + g_part[t + 256];
    __syncthreads();
    for (int off = 128; off > 0; off >>= 1) {
        if (t < off) sf[t] += sf[t + off];
        __syncthreads();
    }
    if (t == 0) g_scal[0] = sf[0];
}

__global__ void k_scat(const int* __restrict__ eidx, const float* __restrict__ ew) {
    int e = blockIdx.x * blockDim.x + threadIdx.x;
    if (e >= ET) return;
    int s, d;
    float a;
    if (e < NE) {
        s = eidx[e];
        d = eidx[NE + e];
        a = ew[e];
    } else {
        s = d = e - NE;
        a = g_scal[0] * (1.0f / (float)NE);
    }
    int p = atomicAdd(&g_pos[d], 1) + g_bpre[d >> 8];
    g_edge[p] = (unsigned)s |
                ((unsigned)__half_as_ushort(__float2half_rn(a)) << 16);
}

// ---------------- per-warp segment aggregation core ----------------
__device__ __forceinline__ void agg_node(int n, int lane, float c,
                                         const __half* __restrict__ hh_in,
                                         const float* __restrict__ asrc_in,
                                         float adstn,
                                         float& ox, float& oy) {
    int start = g_rofs[n] + g_bpre[n >> 8];
    int n2 = n + 1;
    int end = (n2 == NN) ? ET : g_rofs[n2] + g_bpre[n2 >> 8];
    float accx = 0.f, accy = 0.f, ssum = 0.f;

    for (int base = start; base < end; base += 32) {
        int i = base + lane;
        int s_l = 0;
        float alpha = 0.f;
        if (i < end) {
            unsigned ev = g_edge[i];
            s_l = (int)(ev & 0xFFFFu);
            float ea = __half2float(__ushort_as_half((unsigned short)(ev >> 16)));
            float al = asrc_in[s_l] + adstn + ea * c;
            al = fmaxf(al, 0.f) + SLOPE * fminf(al, 0.f);
            alpha = __expf(al);
        }
        ssum += alpha;
        int cnt = min(32, end - base);
        int jj = 0;
        for (; jj + 8 <= cnt; jj += 8) {
            __half2 hv[8];
            float aj[8];
            #pragma unroll
            for (int u = 0; u < 8; u++) {
                int sj = __shfl_sync(0xffffffffu, s_l, jj + u);
                aj[u]  = __shfl_sync(0xffffffffu, alpha, jj + u);
                hv[u] = *reinterpret_cast<const __half2*>(
                    &hh_in[((size_t)sj << 6) + (lane << 1)]);
            }
            #pragma unroll
            for (int u = 0; u < 8; u++) {
                float2 f = __half22float2(hv[u]);
                accx = fmaf(aj[u], f.x, accx);
                accy = fmaf(aj[u], f.y, accy);
            }
        }
        for (; jj < cnt; jj++) {
            int   sj = __shfl_sync(0xffffffffu, s_l, jj);
            float a2 = __shfl_sync(0xffffffffu, alpha, jj);
            float2 f = __half22float2(*reinterpret_cast<const __half2*>(
                &hh_in[((size_t)sj << 6) + (lane << 1)]));
            accx = fmaf(a2, f.x, accx);
            accy = fmaf(a2, f.y, accy);
        }
    }
    #pragma unroll
    for (int off = 16; off > 0; off >>= 1)
        ssum += __shfl_xor_sync(0xffffffffu, ssum, off);
    float inv = 1.f / (ssum + 1e-16f);
    ox = accx * inv;
    oy = accy * inv;
}

// ---------------- layer-1 GEMM (ext input) + logits -> A set ----------------
#define LDA 136
#define LDB 72
#define LDC 68

__global__ void k_gemm1(const float* __restrict__ X, const float* __restrict__ W,
                        const float* __restrict__ as_, const float* __restrict__ ad_) {
    __shared__ __align__(16) char sbuf[18432 + 17408];
    __half* Bs = reinterpret_cast<__half*>(sbuf);
    __half* As = reinterpret_cast<__half*>(sbuf + 18432);
    float*  Cs = reinterpret_cast<float*>(sbuf + 18432);

    int t = threadIdx.x;
    int w = t >> 5;
    int n0 = blockIdx.x * 64;

    {
        int r = t >> 1;
        int n = n0 + r;
        const float4* xrow = reinterpret_cast<const float4*>(X + (size_t)n * FIN);
        #pragma unroll
        for (int f = 0; f < 16; f++) {
            int c4 = (t & 1) * 16 + f;
            float4 v = (n < NN) ? xrow[c4] : make_float4(0, 0, 0, 0);
            __half2* p = reinterpret_cast<__half2*>(&As[r * LDA + c4 * 4]);
            p[0] = __floats2half2_rn(v.x, v.y);
            p[1] = __floats2half2_rn(v.z, v.w);
        }
        const float4* w4 = reinterpret_cast<const float4*>(W);
        for (int idx = t; idx < FIN * HID / 4; idx += 128) {
            int rr = idx >> 4, c4 = idx & 15;
            float4 v = w4[idx];
            __half2* p = reinterpret_cast<__half2*>(&Bs[rr * LDB + c4 * 4]);
            p[0] = __floats2half2_rn(v.x, v.y);
            p[1] = __floats2half2_rn(v.z, v.w);
        }
    }
    __syncthreads();

    wmma::fragment<wmma::accumulator, 16, 16, 16, float> acc[4];
    #pragma unroll
    for (int nt = 0; nt < 4; nt++) wmma::fill_fragment(acc[nt], 0.f);
    for (int kt = 0; kt < FIN / 16; kt++) {
        wmma::fragment<wmma::matrix_a, 16, 16, 16, __half, wmma::row_major> af;
        wmma::load_matrix_sync(af, &As[(w * 16) * LDA + kt * 16], LDA);
        #pragma unroll
        for (int nt = 0; nt < 4; nt++) {
            wmma::fragment<wmma::matrix_b, 16, 16, 16, __half, wmma::row_major> bf;
            wmma::load_matrix_sync(bf, &Bs[(kt * 16) * LDB + nt * 16], LDB);
            wmma::mma_sync(acc[nt], af, bf, acc[nt]);
        }
    }
    __syncthreads();
    #pragma unroll
    for (int nt = 0; nt < 4; nt++)
        wmma::store_matrix_sync(&Cs[(w * 16) * LDC + nt * 16], acc[nt], LDC,
                                wmma::mem_row_major);
    __syncthreads();

    {
        int r = t >> 1;
        int n = n0 + r;
        int cbase = (t & 1) * 32;
        float s = 0.f, d = 0.f;
        if (n < NN) {
            #pragma unroll
            for (int c = 0; c < 32; c += 2) {
                int col = cbase + c;
                float v0 = Cs[r * LDC + col];
                float v1 = Cs[r * LDC + col + 1];
                *reinterpret_cast<__half2*>(&g_hhA[((size_t)n << 6) + col]) =
                    __floats2half2_rn(v0, v1);
                s = fmaf(v0, as_[col], s); s = fmaf(v1, as_[col + 1], s);
                d = fmaf(v0, ad_[col], d); d = fmaf(v1, ad_[col + 1], d);
            }
        }
        s += __shfl_xor_sync(0xffffffffu, s, 1);
        d += __shfl_xor_sync(0xffffffffu, d, 1);
        if ((t & 1) == 0 && n < NN) {
            g_asrcA[n] = s;
            g_adstA[n] = d;
        }
    }
}

// ---------------- FUSED agg + GEMM (HID->HID) + logits ----------------
// 512 threads: 16 warps, warp w aggregates nodes n0+4w..n0+4w+3 into As,
// then block does 64x64 HMMA, epilogue writes hh_out/logits (ping-pong).
__global__ void __launch_bounds__(512) k_agge(
    int layer,
    const __half* __restrict__ hh_in, const float* __restrict__ asrc_in,
    const float* __restrict__ adst_in,
    __half* __restrict__ hh_out, float* __restrict__ asrc_out,
    float* __restrict__ adst_out,
    const float* __restrict__ W, const float* __restrict__ bias_prev,
    const float* __restrict__ as_, const float* __restrict__ ad_) {
    __shared__ __align__(16) char sbuf[9216 + 17408];   // Bs[64][72] + As[64][136]
    __half* Bs = reinterpret_cast<__half*>(sbuf);
    __half* As = reinterpret_cast<__half*>(sbuf + 9216);
    float*  Cs = reinterpret_cast<float*>(sbuf);        // [64][68] alias (post-MMA)

    int t = threadIdx.x;
    int w = t >> 5;
    int lane = t & 31;
    int n0 = blockIdx.x * 64;
    float c = g_scal[1 + layer];
    float b0v = bias_prev[lane << 1];
    float b1v = bias_prev[(lane << 1) + 1];

    // ---- load W while aggregating would race smem; W load first (cheap) ----
    {
        const float4* w4 = reinterpret_cast<const float4*>(W);
        for (int idx = t; idx < HID * HID / 4; idx += 512) {
            int rr = idx >> 4, c4 = idx & 15;
            float4 v = w4[idx];
            __half2* p = reinterpret_cast<__half2*>(&Bs[rr * LDB + c4 * 4]);
            p[0] = __floats2half2_rn(v.x, v.y);
            p[1] = __floats2half2_rn(v.z, v.w);
        }
    }

    // ---- aggregate 4 nodes per warp into As (relu(out+bias) fp16) ----
    #pragma unroll
    for (int m = 0; m < 4; m++) {
        int r = w * 4 + m;
        int n = n0 + r;
        float ox = 0.f, oy = 0.f;
        if (n < NN)
            agg_node(n, lane, c, hh_in, asrc_in, adst_in[n], ox, oy);
        ox = fmaxf(ox + b0v, 0.f);
        oy = fmaxf(oy + b1v, 0.f);
        *reinterpret_cast<__half2*>(&As[r * LDA + (lane << 1)]) =
            __floats2half2_rn(ox, oy);
    }
    __syncthreads();

    // ---- 64x64 HMMA: warp (rt, ct) computes one 16x16 tile ----
    int rt = w >> 2, ct = w & 3;
    wmma::fragment<wmma::accumulator, 16, 16, 16, float> acc;
    wmma::fill_fragment(acc, 0.f);
    #pragma unroll
    for (int kt = 0; kt < HID / 16; kt++) {
        wmma::fragment<wmma::matrix_a, 16, 16, 16, __half, wmma::row_major> af;
        wmma::fragment<wmma::matrix_b, 16, 16, 16, __half, wmma::row_major> bf;
        wmma::load_matrix_sync(af, &As[(rt * 16) * LDA + kt * 16], LDA);
        wmma::load_matrix_sync(bf, &Bs[(kt * 16) * LDB + ct * 16], LDB);
        wmma::mma_sync(acc, af, bf, acc);
    }
    __syncthreads();
    wmma::store_matrix_sync(&Cs[(rt * 16) * LDC + ct * 16], acc, LDC,
                            wmma::mem_row_major);
    __syncthreads();

    // ---- epilogue: h fp16 + logits (8 threads per row, 8 cols each) ----
    {
        int r = t >> 3;
        int n = n0 + r;
        int cbase = (t & 7) * 8;
        float s = 0.f, d = 0.f;
        if (n < NN) {
            #pragma unroll
            for (int cc = 0; cc < 8; cc += 2) {
                int col = cbase + cc;
                float v0 = Cs[r * LDC + col];
                float v1 = Cs[r * LDC + col + 1];
                *reinterpret_cast<__half2*>(&hh_out[((size_t)n << 6) + col]) =
                    __floats2half2_rn(v0, v1);
                s = fmaf(v0, as_[col], s); s = fmaf(v1, as_[col + 1], s);
                d = fmaf(v0, ad_[col], d); d = fmaf(v1, ad_[col + 1], d);
            }
        }
        #pragma unroll
        for (int off = 4; off > 0; off >>= 1) {
            s += __shfl_down_sync(0xffffffffu, s, off, 8);
            d += __shfl_down_sync(0xffffffffu, d, off, 8);
        }
        if ((t & 7) == 0 && n < NN) {
            asrc_out[n] = s;
            adst_out[n] = d;
        }
    }
}

// ---------------- final agg (layer 2) + pooling ----------------
__global__ void k_aggp(const int* __restrict__ batch,
                       const float* __restrict__ bias_last) {
    int n = blockIdx.x * 8 + (threadIdx.x >> 5);
    int lane = threadIdx.x & 31;
    float c = g_scal[3];
    float ox, oy;
    agg_node(n, lane, c, g_hhA, g_asrcA, g_adstA[n], ox, oy);
    int g = batch[n];
    float2 bb = *reinterpret_cast<const float2*>(&bias_last[lane << 1]);
    float* p = &g_pooled[((size_t)g << 6) + (lane << 1)];
    asm volatile("red.global.add.v2.f32 [%0], {%1,%2};"
                 :: "l"(p), "f"(ox + bb.x), "f"(oy + bb.y) : "memory");
    if (lane == 0) atomicAdd(&g_gcnt[g], 1.f);
}

// ---------------- readout ----------------
__global__ void k_read(const float* __restrict__ lin_w,
                       const float* __restrict__ lin_b, float* __restrict__ outp) {
    __shared__ float r[64];
    int g = blockIdx.x, j = threadIdx.x;
    float cnt = fmaxf(g_gcnt[g], 1.f);
    r[j] = (g_pooled[(size_t)g * HID + j] / cnt) * lin_w[j];
    __syncthreads();
    for (int off = 32; off > 0; off >>= 1) {
        if (j < off) r[j] += r[j + off];
        __syncthreads();
    }
    if (j == 0) {
        float v = r[0] + lin_b[0];
        outp[g] = 1.f / (1.f + expf(-v));
    }
}

// ---------------- stream/event resources (static init) ----------------
static cudaStream_t g_stream2;
static cudaEvent_t  g_evFork, g_evGemm1, g_evPre;
namespace {
struct InitRes {
    InitRes() {
        cudaStreamCreateWithFlags(&g_stream2, cudaStreamNonBlocking);
        cudaEventCreateWithFlags(&g_evFork,  cudaEventDisableTiming);
        cudaEventCreateWithFlags(&g_evGemm1, cudaEventDisableTiming);
        cudaEventCreateWithFlags(&g_evPre,   cudaEventDisableTiming);
    }
};
InitRes g_initres;
}

// ---------------- launch ----------------
extern "C" void kernel_launch(void* const* d_in, const int* in_sizes, int n_in,
                              void* d_out, int out_size) {
    const float* x     = (const float*)d_in[0];
    const int*   eidx  = (const int*)  d_in[1];
    const float* ew    = (const float*)d_in[2];
    const int*   batch = (const int*)  d_in[3];
    const float* W[3]  = {(const float*)d_in[4],  (const float*)d_in[10], (const float*)d_in[16]};
    const float* as_[3]= {(const float*)d_in[5],  (const float*)d_in[11], (const float*)d_in[17]};
    const float* ad_[3]= {(const float*)d_in[6],  (const float*)d_in[12], (const float*)d_in[18]};
    const float* We[3] = {(const float*)d_in[7],  (const float*)d_in[13], (const float*)d_in[19]};
    const float* ae[3] = {(const float*)d_in[8],  (const float*)d_in[14], (const float*)d_in[20]};
    const float* b[3]  = {(const float*)d_in[9],  (const float*)d_in[15], (const float*)d_in[21]};
    const float* lin_w = (const float*)d_in[22];
    const float* lin_b = (const float*)d_in[23];
    float* outp = (float*)d_out;

    const int TILE_BLOCKS = (NN + 63) / 64;   // 782
    const int WARP_BLOCKS = NN / 8;           // 6250

    __half *hhA = nullptr, *hhB = nullptr;
    float *asA = nullptr, *asB = nullptr, *adA = nullptr, *adB = nullptr;
    cudaGetSymbolAddress((void**)&hhA, g_hhA);
    cudaGetSymbolAddress((void**)&hhB, g_hhB);
    cudaGetSymbolAddress((void**)&asA, g_asrcA);
    cudaGetSymbolAddress((void**)&asB, g_asrcB);
    cudaGetSymbolAddress((void**)&adA, g_adstA);
    cudaGetSymbolAddress((void**)&adB, g_adstB);

    // fork stream2: pre first (unblocks scan), then gemm1
    cudaEventRecord(g_evFork, 0);
    cudaStreamWaitEvent(g_stream2, g_evFork, 0);
    k_pre<<<PRE_BLOCKS, 256, 0, g_stream2>>>(We[0], ae[0], We[1], ae[1],
                                             We[2], ae[2], ew);
    cudaEventRecord(g_evPre, g_stream2);
    k_gemm1<<<TILE_BLOCKS, 128, 0, g_stream2>>>(x, W[0], as_[0], ad_[0]);
    cudaEventRecord(g_evGemm1, g_stream2);

    // capture stream: hist immediately, then scan (needs pre), scat
    k_hist<<<(NE / 4 + 255) / 256, 256>>>(eidx);
    cudaStreamWaitEvent(0, g_evPre, 0);
    k_s12<<<NCHUNK, 256>>>();
    k_scat<<<(ET + 255) / 256, 256>>>(eidx, ew);

    cudaStreamWaitEvent(0, g_evGemm1, 0);
    // fused: agg layer0 (reads A) + gemm2 (writes B)
    k_agge<<<TILE_BLOCKS, 512>>>(0, hhA, asA, adA, hhB, asB, adB,
                                 W[1], b[0], as_[1], ad_[1]);
    // fused: agg layer1 (reads B) + gemm3 (writes A)
    k_agge<<<TILE_BLOCKS, 512>>>(1, hhB, asB, adB, hhA, asA, adA,
                                 W[2], b[1], as_[2], ad_[2]);
    // final agg (reads A) + pool
    k_aggp<<<WARP_BLOCKS, 256>>>(batch, b[2]);
    k_read<<<NG, 64>>>(lin_w, lin_b, outp);
}